// round 6
// baseline (speedup 1.0000x reference)
#include <cuda_runtime.h>
#include <cuda_bf16.h>
#include <cstdint>

#define HIDDEN   7168
#define NEXPERTS 256
#define TOPK     8
#define NGROUP   8
#define TOPKGRP  4
#define SCALING  2.5f

#define BM 128
#define BN 128
#define BK 8
#define MAX_T 8192

// scratch: router logits [T, 256]
__device__ float g_logits[MAX_T * NEXPERTS];

// ---------------------------------------------------------------------------
// packed f32x2 helpers (Blackwell FFMA2 — only reachable via PTX)
// ---------------------------------------------------------------------------
__device__ __forceinline__ void fma2(unsigned long long& d,
                                     unsigned long long a,
                                     unsigned long long b) {
    asm("fma.rn.f32x2 %0, %1, %2, %0;" : "+l"(d) : "l"(a), "l"(b));
}
__device__ __forceinline__ unsigned long long dup2(float a) {
    unsigned long long p;
    asm("mov.b64 %0, {%1, %1};" : "=l"(p) : "f"(a));
    return p;
}
__device__ __forceinline__ void unpack2(unsigned long long p, float& lo, float& hi) {
    asm("mov.b64 {%0, %1}, %2;" : "=f"(lo), "=f"(hi) : "l"(p));
}

// ---------------------------------------------------------------------------
// GEMM: logits = x @ W^T   (fp32 exact, f32x2-packed FMAs)
// grid: (T/BM, NEXPERTS/BN), block: 256 threads
// ---------------------------------------------------------------------------
__global__ void __launch_bounds__(256)
router_gemm_kernel(const float* __restrict__ A,   // x [T, HIDDEN]
                   const float* __restrict__ B,   // weight [256, HIDDEN]
                   int T) {
    __shared__ unsigned long long As[BK][BM];  // duplicated pairs (a,a): 8KB
    __shared__ float              Bs[BK][BN];  // 4KB

    const int tid = threadIdx.x;
    const int tx  = tid & 15;   // 0..15 -> experts 2*tx + 32*p
    const int ty  = tid >> 4;   // 0..15 -> tokens ty*8 + m
    const int rowBase = blockIdx.x * BM;
    const int colBase = blockIdx.y * BN;

    const int lrow = tid >> 1;          // 0..127
    const int lcol = (tid & 1) * 4;     // 0 or 4

    const float* Aptr = A + (size_t)(rowBase + lrow) * HIDDEN + lcol;
    const float* Bptr = B + (size_t)(colBase + lrow) * HIDDEN + lcol;

    unsigned long long acc[8][4];
#pragma unroll
    for (int m = 0; m < 8; m++)
#pragma unroll
        for (int p = 0; p < 4; p++) acc[m][p] = 0ull;

    const int kTiles = HIDDEN / BK;  // 896

    float4 aReg = *reinterpret_cast<const float4*>(Aptr);
    float4 bReg = *reinterpret_cast<const float4*>(Bptr);

    for (int t = 0; t < kTiles; ++t) {
        // store staged regs into smem (A duplicated)
        As[lcol + 0][lrow] = dup2(aReg.x);
        As[lcol + 1][lrow] = dup2(aReg.y);
        As[lcol + 2][lrow] = dup2(aReg.z);
        As[lcol + 3][lrow] = dup2(aReg.w);
        Bs[lcol + 0][lrow] = bReg.x;
        Bs[lcol + 1][lrow] = bReg.y;
        Bs[lcol + 2][lrow] = bReg.z;
        Bs[lcol + 3][lrow] = bReg.w;
        __syncthreads();

        // prefetch next tile while computing this one
        if (t + 1 < kTiles) {
            aReg = *reinterpret_cast<const float4*>(Aptr + (t + 1) * BK);
            bReg = *reinterpret_cast<const float4*>(Bptr + (t + 1) * BK);
        }

#pragma unroll
        for (int k = 0; k < BK; ++k) {
            const ulonglong2* ap =
                reinterpret_cast<const ulonglong2*>(&As[k][ty * 8]);
            ulonglong2 a01 = ap[0], a23 = ap[1], a45 = ap[2], a67 = ap[3];
            unsigned long long a[8] = {a01.x, a01.y, a23.x, a23.y,
                                       a45.x, a45.y, a67.x, a67.y};
            unsigned long long b[4];
#pragma unroll
            for (int p = 0; p < 4; p++)
                b[p] = *reinterpret_cast<const unsigned long long*>(
                    &Bs[k][2 * tx + 32 * p]);

#pragma unroll
            for (int m = 0; m < 8; m++)
#pragma unroll
                for (int p = 0; p < 4; p++)
                    fma2(acc[m][p], a[m], b[p]);
        }
        __syncthreads();
    }

    // epilogue: write logits (coalesced float2 across tx)
#pragma unroll
    for (int m = 0; m < 8; m++) {
        const int row = rowBase + ty * 8 + m;
        float* orow = g_logits + (size_t)row * NEXPERTS + colBase + 2 * tx;
#pragma unroll
        for (int p = 0; p < 4; p++) {
            float lo, hi;
            unpack2(acc[m][p], lo, hi);
            *reinterpret_cast<float2*>(orow + 32 * p) = make_float2(lo, hi);
        }
    }
}

// ---------------------------------------------------------------------------
// Routing: one warp per token.
// out layout: [0, T*8)   = topk indices (as float)
//             [T*8, 2T*8)= topk weights
// ---------------------------------------------------------------------------
__global__ void __launch_bounds__(256)
routing_kernel(const float* __restrict__ bias, float* __restrict__ out, int T) {
    const int warp = (blockIdx.x * blockDim.x + threadIdx.x) >> 5;
    const int lane = threadIdx.x & 31;
    if (warp >= T) return;

    const float NEG_INF = __int_as_float(0xff800000);
    const float* lrow = g_logits + (size_t)warp * NEXPERTS;

    // each lane owns experts [lane*8, lane*8+8)
    float4 l0 = *reinterpret_cast<const float4*>(lrow + lane * 8);
    float4 l1 = *reinterpret_cast<const float4*>(lrow + lane * 8 + 4);
    float4 b0 = *reinterpret_cast<const float4*>(bias + lane * 8);
    float4 b1 = *reinterpret_cast<const float4*>(bias + lane * 8 + 4);

    float lg[8] = {l0.x, l0.y, l0.z, l0.w, l1.x, l1.y, l1.z, l1.w};
    float bb[8] = {b0.x, b0.y, b0.z, b0.w, b1.x, b1.y, b1.z, b1.w};

    float s[8], sc[8];
#pragma unroll
    for (int j = 0; j < 8; j++) {
        s[j]  = 1.0f / (1.0f + expf(-lg[j]));  // sigmoid score
        sc[j] = s[j] + bb[j];                  // score + correction bias
    }

    // --- group scores: top-2 sum within each group of 32 experts (4 lanes) ---
    float m1 = NEG_INF, m2 = NEG_INF;
#pragma unroll
    for (int j = 0; j < 8; j++) {
        float v = sc[j];
        if (v > m1) { m2 = m1; m1 = v; }
        else if (v > m2) { m2 = v; }
    }
#pragma unroll
    for (int off = 1; off <= 2; off <<= 1) {
        float om1 = __shfl_xor_sync(0xffffffffu, m1, off);
        float om2 = __shfl_xor_sync(0xffffffffu, m2, off);
        float n1 = fmaxf(m1, om1);
        float n2 = fmaxf(fminf(m1, om1), fmaxf(m2, om2));
        m1 = n1; m2 = n2;
    }
    const float gscore = m1 + m2;  // identical on all 4 lanes of the group

    // gather all 8 group scores
    float gs[8];
#pragma unroll
    for (int g = 0; g < 8; g++)
        gs[g] = __shfl_sync(0xffffffffu, gscore, g * 4);

    // is my group in the top-4? (tie -> lower group index wins)
    const int myg = lane >> 2;
    const float mygs = gs[myg];
    int rank = 0;
#pragma unroll
    for (int g = 0; g < 8; g++)
        rank += (gs[g] > mygs) || (gs[g] == mygs && g < myg);
    const bool sel = (rank < TOPKGRP);

    float msc[8];
#pragma unroll
    for (int j = 0; j < 8; j++) msc[j] = sel ? sc[j] : 0.0f;

    // --- iterative top-8 over masked scores (tie -> lower index) ---
    float wv[TOPK];
    int   wi[TOPK];
    float sum_s = 0.0f;

#pragma unroll
    for (int it = 0; it < TOPK; it++) {
        float bv = msc[0];
        int   bj = 0;
#pragma unroll
        for (int j = 1; j < 8; j++)
            if (msc[j] > bv) { bv = msc[j]; bj = j; }
        int   bidx = lane * 8 + bj;
        float bs   = s[bj];

#pragma unroll
        for (int off = 16; off >= 1; off >>= 1) {
            float ov = __shfl_xor_sync(0xffffffffu, bv, off);
            int   oi = __shfl_xor_sync(0xffffffffu, bidx, off);
            float os = __shfl_xor_sync(0xffffffffu, bs, off);
            if (ov > bv || (ov == bv && oi < bidx)) { bv = ov; bidx = oi; bs = os; }
        }
        // all lanes agree on the winner now
        wv[it] = bs;
        wi[it] = bidx;
        sum_s += bs;
        if ((bidx >> 3) == lane) msc[bidx & 7] = NEG_INF;  // remove winner
    }

    if (lane == 0) {
        const float inv = SCALING / (sum_s + 1e-20f);
        float* oidx = out + (size_t)warp * TOPK;
        float* ow   = out + (size_t)T * TOPK + (size_t)warp * TOPK;
#pragma unroll
        for (int it = 0; it < TOPK; it++) {
            oidx[it] = (float)wi[it];
            ow[it]   = wv[it] * inv;
        }
    }
}

// ---------------------------------------------------------------------------
extern "C" void kernel_launch(void* const* d_in, const int* in_sizes, int n_in,
                              void* d_out, int out_size) {
    const float* x    = (const float*)d_in[0];
    const float* w    = (const float*)d_in[1];
    const float* bias = (const float*)d_in[2];
    float* out = (float*)d_out;

    const int T = in_sizes[0] / HIDDEN;  // 8192

    dim3 grid(T / BM, NEXPERTS / BN);    // 64 x 2
    router_gemm_kernel<<<grid, 256>>>(x, w, T);

    const int warpsPerBlock = 256 / 32;
    routing_kernel<<<(T + warpsPerBlock - 1) / warpsPerBlock, 256>>>(bias, out, T);
}